// round 12
// baseline (speedup 1.0000x reference)
#include <cuda_runtime.h>
#include <cuda_fp16.h>
#include <cstdint>

// CosSimilarity via fp16 mma.sync (legacy HMMA; tcgen05 unavailable: harness
// ptxas targets plain sm_103).
//  SINGLE fused persistent kernel (R12):
//   phase 1 (per-warp): normalize rows (x pre-scaled by 1/TEMP=20) -> fp16
//     scratch; per-128-row-block completion counters (g_cnt, count-up).
//   phase 2: R8 mainloop — persistent HMMA GEMM, BM=BN=128, BK=64, 3-stage
//     mbarrier cp.async pipeline, 4 warps/CTA (2x2 of 64x64), 2 CTA/SM.
//     Producer spins on the two block counters when starting each tile ->
//     GEMM overlaps the tail of normalization. All 296 CTAs co-resident.
//  g_cnt zeroed each launch via cudaMemsetAsync (graph-capturable).

#define NROWS 4096
#define DDIM  1024
#define BM 128
#define BN 128
#define BK 64
#define NSTAGE 3
#define KITERS (DDIM / BK)              // 16
#define STAGE_BYTES ((BM + BN) * 128)   // 32 KB
#define SMEM_ST0 1024
#define SMEM_DYN (SMEM_ST0 + NSTAGE * STAGE_BYTES)
#define NTILES ((NROWS / BM) * (NROWS / BN))   // 1024
#define GRID_P 296                      // 2 x 148 SMs (all co-resident)
#define NTHREADS 128

__device__ __align__(1024) __half g_xh[NROWS * DDIM];
__device__ __align__(1024) __half g_yh[NROWS * DDIM];
__device__ int g_cnt[64];               // per-128-row-block completion (0..128)

__device__ __forceinline__ uint32_t smem_u32(const void* p) {
    uint32_t a;
    asm("{ .reg .u64 t; cvta.to.shared.u64 t, %1; cvt.u32.u64 %0, t; }" : "=r"(a) : "l"(p));
    return a;
}

#define CP_ASYNC16(dst, src) \
    asm volatile("cp.async.cg.shared.global [%0], [%1], 16;" :: "r"(dst), "l"(src))
#define CP_ASYNC_ARRIVE_NOINC(mbar) \
    asm volatile("cp.async.mbarrier.arrive.noinc.shared.b64 [%0];" :: "r"(mbar) : "memory")

#define MBAR_INIT(addr, cnt) \
    asm volatile("mbarrier.init.shared.b64 [%0], %1;" :: "r"(addr), "r"(cnt) : "memory")
#define MBAR_ARRIVE(addr) \
    asm volatile("mbarrier.arrive.shared.b64 _, [%0];" :: "r"(addr) : "memory")

#define MBAR_WAIT(addr, par) do {                                                  \
    uint32_t _m = (addr); uint32_t _p = (par); uint32_t _done;                     \
    asm volatile("{\n\t.reg .pred p;\n\t"                                          \
        "mbarrier.try_wait.parity.acquire.cta.shared::cta.b64 p, [%1], %2;\n\t"    \
        "selp.b32 %0, 1, 0, p;\n\t}"                                               \
        : "=r"(_done) : "r"(_m), "r"(_p) : "memory");                              \
    if (!_done) {                                                                  \
        asm volatile("{\n\t.reg .pred P1;\n\t"                                     \
            "WL_%=:\n\t"                                                           \
            "mbarrier.try_wait.parity.acquire.cta.shared::cta.b64 P1, [%0], %1, 0x989680;\n\t" \
            "@P1 bra.uni WD_%=;\n\t"                                               \
            "bra.uni WL_%=;\n\t"                                                   \
            "WD_%=:\n\t}" :: "r"(_m), "r"(_p) : "memory");                         \
    }                                                                              \
} while (0)

#define MBAR_WAIT_RLX(addr, par) do {                                              \
    uint32_t _m = (addr); uint32_t _p = (par); uint32_t _done;                     \
    asm volatile("{\n\t.reg .pred p;\n\t"                                          \
        "mbarrier.try_wait.parity.relaxed.cta.shared::cta.b64 p, [%1], %2, 0x989680;\n\t" \
        "selp.b32 %0, 1, 0, p;\n\t}"                                               \
        : "=r"(_done) : "r"(_m), "r"(_p) : "memory");                              \
    if (!_done) {                                                                  \
        asm volatile("{\n\t.reg .pred P1;\n\t"                                     \
            "WL_%=:\n\t"                                                           \
            "mbarrier.try_wait.parity.relaxed.cta.shared::cta.b64 P1, [%0], %1, 0x989680;\n\t" \
            "@P1 bra.uni WD_%=;\n\t"                                               \
            "bra.uni WL_%=;\n\t"                                                   \
            "WD_%=:\n\t}" :: "r"(_m), "r"(_p) : "memory");                         \
    }                                                                              \
} while (0)

__device__ __forceinline__ uint32_t swz(uint32_t off) {
    return off ^ ((off >> 3) & 0x70);
}

__device__ __forceinline__ void ldsm_x4(uint32_t* r, uint32_t addr) {
    asm volatile("ldmatrix.sync.aligned.m8n8.x4.shared.b16 {%0,%1,%2,%3}, [%4];"
                 : "=r"(r[0]), "=r"(r[1]), "=r"(r[2]), "=r"(r[3]) : "r"(addr));
}

__device__ __forceinline__ void mma16816(float* c, const uint32_t* a, const uint32_t* b) {
    asm volatile(
        "mma.sync.aligned.m16n8k16.row.col.f32.f16.f16.f32 "
        "{%0,%1,%2,%3}, {%4,%5,%6,%7}, {%8,%9}, {%0,%1,%2,%3};"
        : "+f"(c[0]), "+f"(c[1]), "+f"(c[2]), "+f"(c[3])
        : "r"(a[0]), "r"(a[1]), "r"(a[2]), "r"(a[3]), "r"(b[0]), "r"(b[1]));
}

// ---------------------------------------------------------------------------
// Fused kernel: norm phase (per-warp) + persistent HMMA GEMM
// ---------------------------------------------------------------------------
__global__ void __launch_bounds__(NTHREADS, 2)
fused_kernel(const float* __restrict__ x, const float* __restrict__ y,
             float* __restrict__ C) {
    extern __shared__ __align__(1024) char smem[];
    const uint32_t smem_base = smem_u32(smem);
    const int tid = threadIdx.x;
    const int wid = tid >> 5;
    const int lid = tid & 31;

    // barriers: full[s] @ base + s*8 ; empty[s] @ base + 24 + s*8
    if (tid == 0) {
        #pragma unroll
        for (int s = 0; s < NSTAGE; s++) {
            MBAR_INIT(smem_base + s * 8, NTHREADS); // full: one noinc arrive/thread
            MBAR_INIT(smem_base + 24 + s * 8, 4);   // empty: one arrive/warp
        }
    }
    __syncthreads();

    // ---------------- Phase 1: per-warp row normalization ----------------
    {
        const int gw = blockIdx.x * 4 + wid;       // 0..1183
        for (int row = gw; row < 2 * NROWS; row += GRID_P * 4) {
            const float4* src; __half2* dst; float extra; int cb;
            if (row < NROWS) {
                src = (const float4*)(x + (size_t)row * DDIM);
                dst = (__half2*)(g_xh + (size_t)row * DDIM);
                extra = 20.0f;                      // 1/TEMP folded into x side
                cb = row >> 7;
            } else {
                int r = row - NROWS;
                src = (const float4*)(y + (size_t)r * DDIM);
                dst = (__half2*)(g_yh + (size_t)r * DDIM);
                extra = 1.0f;
                cb = 32 + (r >> 7);
            }
            float4 v[8];
            float ss = 0.0f;
            #pragma unroll
            for (int j = 0; j < 8; j++) {
                v[j] = src[j * 32 + lid];
                ss += v[j].x * v[j].x + v[j].y * v[j].y
                    + v[j].z * v[j].z + v[j].w * v[j].w;
            }
            #pragma unroll
            for (int o = 16; o > 0; o >>= 1)
                ss += __shfl_xor_sync(0xffffffffu, ss, o);
            float inv = extra / fmaxf(sqrtf(ss), 1e-8f);
            #pragma unroll
            for (int j = 0; j < 8; j++) {
                int k = j * 32 + lid;
                dst[2 * k]     = __floats2half2_rn(v[j].x * inv, v[j].y * inv);
                dst[2 * k + 1] = __floats2half2_rn(v[j].z * inv, v[j].w * inv);
            }
            __threadfence();
            __syncwarp();
            if (lid == 0) atomicAdd(&g_cnt[cb], 1);
        }
    }

    // ---------------- Phase 2: persistent GEMM (R8 mainloop) ----------------
    const int wm = wid & 1;              // m band (64 rows each)
    const int wn = wid >> 1;             // n band (64 cols each)

    // ldmatrix lane geometry
    const int g   = lid >> 3;
    const int rin = lid & 7;
    const int a_m  = (g & 1) * 8 + rin;
    const int a_kb = (g >> 1) * 16;
    const int b_n  = (g >> 1) * 8 + rin;
    const int b_kb = (g & 1) * 16;

    uint32_t a_rowoff[4], b_rowoff[4];
    #pragma unroll
    for (int t = 0; t < 4; t++)
        a_rowoff[t] = (uint32_t)(wm * 64 + t * 16 + a_m) * 128;
    #pragma unroll
    for (int p = 0; p < 4; p++)
        b_rowoff[p] = (uint32_t)(BM + wn * 64 + p * 16 + b_n) * 128;

    // Stage loader for (tile lt, k-slice lk): 2048 chunks / 128 thr = 16 each.
    // When starting a new tile (lk==0), wait for its operand blocks to be
    // fully normalized (count-up to 128 each).
    auto load_stage = [&](int sbuf, int lt, int lk) {
        if (lk == 0) {
            volatile int* cx = &g_cnt[lt >> 5];
            volatile int* cy = &g_cnt[32 + (lt & 31)];
            while (*cx != 128) { }
            while (*cy != 128) { }
            __threadfence();
        }
        uint32_t sbase = smem_base + SMEM_ST0 + sbuf * STAGE_BYTES;
        const char* ag = (const char*)g_xh
            + ((size_t)(lt >> 5) * BM) * (DDIM * 2) + lk * (BK * 2);
        const char* bg = (const char*)g_yh
            + ((size_t)(lt & 31) * BN) * (DDIM * 2) + lk * (BK * 2);
        #pragma unroll
        for (int k = 0; k < 16; k++) {
            int i = tid + k * NTHREADS;
            int r = (i >> 3) & 127;
            int c = (i & 7) * 16;
            uint32_t off = swz((uint32_t)((i < 1024 ? r : BM + r) * 128 + c));
            const char* src = (i < 1024 ? ag : bg) + (size_t)r * (DDIM * 2) + c;
            CP_ASYNC16(sbase + off, src);
        }
        CP_ASYNC_ARRIVE_NOINC(smem_base + sbuf * 8);
    };

    float acc[4][8][4];
    #pragma unroll
    for (int mt = 0; mt < 4; mt++)
        #pragma unroll
        for (int nt = 0; nt < 8; nt++)
            #pragma unroll
            for (int q = 0; q < 4; q++)
                acc[mt][nt][q] = 0.0f;

    int tile = blockIdx.x;
    int lt = tile, lk = 0;
    // Prologue: stages 0,1 of first tile (fresh empty barriers: no wait needed)
    load_stage(0, lt, 0);
    load_stage(1, lt, 1);
    lk = 2;

    int sb = 0, fpar = 0;     // consumer: buffer + full-parity
    int lb = 2, epar = 1;     // producer: buffer + empty-parity (first waits pass)
    while (tile < NTILES) {
        for (int it = 0; it < KITERS; ++it) {
            // Producer: refill next buffer (waits only on 3-ago consumption)
            if (lt < NTILES) {
                MBAR_WAIT_RLX(smem_base + 24 + lb * 8, epar);
                load_stage(lb, lt, lk);
                if (++lk == KITERS) { lk = 0; lt += GRID_P; }
                if (++lb == NSTAGE) { lb = 0; epar ^= 1; }
            }

            // Consumer: wait for this stage's data
            MBAR_WAIT(smem_base + sb * 8, fpar);

            const uint32_t sbase = smem_base + SMEM_ST0 + sb * STAGE_BYTES;
            #pragma unroll
            for (int ks = 0; ks < 4; ks++) {
                const uint32_t kb = ks * 32;
                uint32_t a[4][4];
                #pragma unroll
                for (int t = 0; t < 4; t++)
                    ldsm_x4(a[t], sbase + swz(a_rowoff[t] + kb + a_kb));
                uint32_t b[8][2];
                #pragma unroll
                for (int p = 0; p < 4; p++) {
                    uint32_t r[4];
                    ldsm_x4(r, sbase + swz(b_rowoff[p] + kb + b_kb));
                    b[2 * p][0] = r[0]; b[2 * p][1] = r[1];
                    b[2 * p + 1][0] = r[2]; b[2 * p + 1][1] = r[3];
                }
                #pragma unroll
                for (int mt = 0; mt < 4; mt++)
                    #pragma unroll
                    for (int nt = 0; nt < 8; nt++)
                        mma16816(acc[mt][nt], a[mt], b[nt]);
            }
            // This warp is done reading stage sb
            __syncwarp();
            if (lid == 0) MBAR_ARRIVE(smem_base + 24 + sb * 8);
            if (++sb == NSTAGE) { sb = 0; fpar ^= 1; }
        }

        // Epilogue for this tile (overlaps in-flight loads of next tile)
        {
            const int rowA0 = (tile >> 5) * BM;
            const int rowB0 = (tile & 31) * BN;
            const int crow = rowA0 + wm * 64 + (lid >> 2);
            const int ccol = rowB0 + wn * 64 + (lid & 3) * 2;
            #pragma unroll
            for (int mt = 0; mt < 4; mt++) {
                #pragma unroll
                for (int nt = 0; nt < 8; nt++) {
                    float* p0 = C + (size_t)(crow + mt * 16) * NROWS + ccol + nt * 8;
                    float* p1 = p0 + 8 * NROWS;
                    *(float2*)p0 = make_float2(acc[mt][nt][0], acc[mt][nt][1]);
                    *(float2*)p1 = make_float2(acc[mt][nt][2], acc[mt][nt][3]);
                    acc[mt][nt][0] = 0.0f; acc[mt][nt][1] = 0.0f;
                    acc[mt][nt][2] = 0.0f; acc[mt][nt][3] = 0.0f;
                }
            }
        }
        tile += GRID_P;
    }
}

// ---------------------------------------------------------------------------
extern "C" void kernel_launch(void* const* d_in, const int* in_sizes, int n_in,
                              void* d_out, int out_size) {
    const float* x = (const float*)d_in[0];
    const float* y = (const float*)d_in[1];
    float* out = (float*)d_out;

    cudaFuncSetAttribute(fused_kernel, cudaFuncAttributeMaxDynamicSharedMemorySize, SMEM_DYN);

    void* cnt_addr = nullptr;
    cudaGetSymbolAddress(&cnt_addr, g_cnt);
    cudaMemsetAsync(cnt_addr, 0, 64 * sizeof(int));

    fused_kernel<<<GRID_P, NTHREADS, SMEM_DYN>>>(x, y, out);
}

// round 13
// speedup vs baseline: 1.1299x; 1.1299x over previous
#include <cuda_runtime.h>
#include <cuda_fp16.h>
#include <cstdint>

// CosSimilarity via fp16 mma.sync (legacy HMMA; tcgen05 unavailable: harness
// ptxas targets plain sm_103).
//  K1: normalize rows (x side pre-scaled by 1/TEMP=20) -> fp16 scratch; also
//      seeds the dynamic-tile counter.
//  K2: persistent HMMA GEMM (R8 config: BM=BN=128, BK=64, 3-stage mbarrier
//      cp.async pipeline, 128-thread CTAs, 2x2 of 64x64 warp tiles, 2 CTA/SM)
//      NEW (R13): dynamic work-stealing tile scheduler. 1024 tiles / 296 CTAs
//      = 3.46 -> static assignment forces a 4-tile makespan (~13.5% idle
//      tail, invariant across R4-R11). A global atomic counter + 8-entry smem
//      tile ring balances the tail to <=1 tile across 148 SMs.

#define NROWS 4096
#define DDIM  1024
#define BM 128
#define BN 128
#define BK 64
#define NSTAGE 3
#define KITERS (DDIM / BK)              // 16
#define STAGE_BYTES ((BM + BN) * 128)   // 32 KB
#define SMEM_ST0 1024
#define SMEM_DYN (SMEM_ST0 + NSTAGE * STAGE_BYTES)
#define NTILES ((NROWS / BM) * (NROWS / BN))   // 1024
#define GRID_P 296                      // 2 x 148 SMs (all co-resident)
#define NTHREADS 128

__device__ __align__(1024) __half g_xh[NROWS * DDIM];
__device__ __align__(1024) __half g_yh[NROWS * DDIM];
__device__ int g_tile_ctr;              // next unassigned tile (seeded = GRID_P)

__device__ __forceinline__ uint32_t smem_u32(const void* p) {
    uint32_t a;
    asm("{ .reg .u64 t; cvta.to.shared.u64 t, %1; cvt.u32.u64 %0, t; }" : "=r"(a) : "l"(p));
    return a;
}

#define CP_ASYNC16(dst, src) \
    asm volatile("cp.async.cg.shared.global [%0], [%1], 16;" :: "r"(dst), "l"(src))
#define CP_ASYNC_ARRIVE_NOINC(mbar) \
    asm volatile("cp.async.mbarrier.arrive.noinc.shared.b64 [%0];" :: "r"(mbar) : "memory")

#define MBAR_INIT(addr, cnt) \
    asm volatile("mbarrier.init.shared.b64 [%0], %1;" :: "r"(addr), "r"(cnt) : "memory")
#define MBAR_ARRIVE(addr) \
    asm volatile("mbarrier.arrive.shared.b64 _, [%0];" :: "r"(addr) : "memory")

#define MBAR_WAIT(addr, par) do {                                                  \
    uint32_t _m = (addr); uint32_t _p = (par); uint32_t _done;                     \
    asm volatile("{\n\t.reg .pred p;\n\t"                                          \
        "mbarrier.try_wait.parity.acquire.cta.shared::cta.b64 p, [%1], %2;\n\t"    \
        "selp.b32 %0, 1, 0, p;\n\t}"                                               \
        : "=r"(_done) : "r"(_m), "r"(_p) : "memory");                              \
    if (!_done) {                                                                  \
        asm volatile("{\n\t.reg .pred P1;\n\t"                                     \
            "WL_%=:\n\t"                                                           \
            "mbarrier.try_wait.parity.acquire.cta.shared::cta.b64 P1, [%0], %1, 0x989680;\n\t" \
            "@P1 bra.uni WD_%=;\n\t"                                               \
            "bra.uni WL_%=;\n\t"                                                   \
            "WD_%=:\n\t}" :: "r"(_m), "r"(_p) : "memory");                         \
    }                                                                              \
} while (0)

#define MBAR_WAIT_RLX(addr, par) do {                                              \
    uint32_t _m = (addr); uint32_t _p = (par); uint32_t _done;                     \
    asm volatile("{\n\t.reg .pred p;\n\t"                                          \
        "mbarrier.try_wait.parity.relaxed.cta.shared::cta.b64 p, [%1], %2, 0x989680;\n\t" \
        "selp.b32 %0, 1, 0, p;\n\t}"                                               \
        : "=r"(_done) : "r"(_m), "r"(_p) : "memory");                              \
    if (!_done) {                                                                  \
        asm volatile("{\n\t.reg .pred P1;\n\t"                                     \
            "WL_%=:\n\t"                                                           \
            "mbarrier.try_wait.parity.relaxed.cta.shared::cta.b64 P1, [%0], %1, 0x989680;\n\t" \
            "@P1 bra.uni WD_%=;\n\t"                                               \
            "bra.uni WL_%=;\n\t"                                                   \
            "WD_%=:\n\t}" :: "r"(_m), "r"(_p) : "memory");                         \
    }                                                                              \
} while (0)

__device__ __forceinline__ uint32_t swz(uint32_t off) {
    return off ^ ((off >> 3) & 0x70);
}

__device__ __forceinline__ void ldsm_x4(uint32_t* r, uint32_t addr) {
    asm volatile("ldmatrix.sync.aligned.m8n8.x4.shared.b16 {%0,%1,%2,%3}, [%4];"
                 : "=r"(r[0]), "=r"(r[1]), "=r"(r[2]), "=r"(r[3]) : "r"(addr));
}

__device__ __forceinline__ void mma16816(float* c, const uint32_t* a, const uint32_t* b) {
    asm volatile(
        "mma.sync.aligned.m16n8k16.row.col.f32.f16.f16.f32 "
        "{%0,%1,%2,%3}, {%4,%5,%6,%7}, {%8,%9}, {%0,%1,%2,%3};"
        : "+f"(c[0]), "+f"(c[1]), "+f"(c[2]), "+f"(c[3])
        : "r"(a[0]), "r"(a[1]), "r"(a[2]), "r"(a[3]), "r"(b[0]), "r"(b[1]));
}

// ---------------------------------------------------------------------------
// Kernel 1: row normalization -> fp16; block 0 seeds the tile counter.
// ---------------------------------------------------------------------------
__global__ void norm_kernel(const float* __restrict__ x, const float* __restrict__ y) {
    if (blockIdx.x == 0 && threadIdx.x == 0) g_tile_ctr = GRID_P;

    int row = blockIdx.x;
    const float4* src; __half2* dst; float extra;
    if (row < NROWS) {
        src = (const float4*)(x + (size_t)row * DDIM);
        dst = (__half2*)(g_xh + (size_t)row * DDIM);
        extra = 20.0f;                  // 1/TEMP folded into x side
    } else {
        int r = row - NROWS;
        src = (const float4*)(y + (size_t)r * DDIM);
        dst = (__half2*)(g_yh + (size_t)r * DDIM);
        extra = 1.0f;
    }
    int t = threadIdx.x;
    float4 v = src[t];
    float ss = v.x * v.x + v.y * v.y + v.z * v.z + v.w * v.w;
    #pragma unroll
    for (int o = 16; o > 0; o >>= 1) ss += __shfl_xor_sync(0xffffffffu, ss, o);

    __shared__ float wss[8];
    __shared__ float sinv;
    if ((t & 31) == 0) wss[t >> 5] = ss;
    __syncthreads();
    if (t == 0) {
        float tot = 0.0f;
        #pragma unroll
        for (int i = 0; i < 8; i++) tot += wss[i];
        sinv = extra / fmaxf(sqrtf(tot), 1e-8f);
    }
    __syncthreads();
    float inv = sinv;
    dst[2 * t]     = __floats2half2_rn(v.x * inv, v.y * inv);
    dst[2 * t + 1] = __floats2half2_rn(v.z * inv, v.w * inv);
}

// ---------------------------------------------------------------------------
// Kernel 2: persistent HMMA GEMM with dynamic tile scheduler
// ---------------------------------------------------------------------------
__global__ void __launch_bounds__(NTHREADS, 2) gemm_kernel(float* __restrict__ C) {
    extern __shared__ __align__(1024) char smem[];
    const uint32_t smem_base = smem_u32(smem);
    const int tid = threadIdx.x;
    const int wid = tid >> 5;
    const int lid = tid & 31;

    const int wm = wid & 1;              // m band (64 rows each)
    const int wn = wid >> 1;             // n band (64 cols each)

    // smem header: full[s] @ +s*8; empty[s] @ +24+s*8; tile ring @ +48 (8 ints)
    volatile int* s_tile = (volatile int*)(smem + 48);
    if (tid == 0) {
        #pragma unroll
        for (int s = 0; s < NSTAGE; s++) {
            MBAR_INIT(smem_base + s * 8, NTHREADS); // full: one noinc arrive/thread
            MBAR_INIT(smem_base + 24 + s * 8, 4);   // empty: one arrive/warp
        }
        s_tile[0] = blockIdx.x;                     // seq 0: static seed
        s_tile[1] = atomicAdd(&g_tile_ctr, 1);      // seq 1: first steal
    }
    __syncthreads();

    // ldmatrix lane geometry
    const int g   = lid >> 3;
    const int rin = lid & 7;
    const int a_m  = (g & 1) * 8 + rin;
    const int a_kb = (g >> 1) * 16;
    const int b_n  = (g >> 1) * 8 + rin;
    const int b_kb = (g & 1) * 16;

    uint32_t a_rowoff[4], b_rowoff[4];
    #pragma unroll
    for (int t = 0; t < 4; t++)
        a_rowoff[t] = (uint32_t)(wm * 64 + t * 16 + a_m) * 128;
    #pragma unroll
    for (int p = 0; p < 4; p++)
        b_rowoff[p] = (uint32_t)(BM + wn * 64 + p * 16 + b_n) * 128;

    // Stage loader for (tile lt, k-slice lk): 2048 chunks / 128 thr = 16 each.
    auto load_stage = [&](int sbuf, int lt, int lk) {
        uint32_t sbase = smem_base + SMEM_ST0 + sbuf * STAGE_BYTES;
        const char* ag = (const char*)g_xh
            + ((size_t)(lt >> 5) * BM) * (DDIM * 2) + lk * (BK * 2);
        const char* bg = (const char*)g_yh
            + ((size_t)(lt & 31) * BN) * (DDIM * 2) + lk * (BK * 2);
        #pragma unroll
        for (int k = 0; k < 16; k++) {
            int i = tid + k * NTHREADS;
            int r = (i >> 3) & 127;
            int c = (i & 7) * 16;
            uint32_t off = swz((uint32_t)((i < 1024 ? r : BM + r) * 128 + c));
            const char* src = (i < 1024 ? ag : bg) + (size_t)r * (DDIM * 2) + c;
            CP_ASYNC16(sbase + off, src);
        }
        CP_ASYNC_ARRIVE_NOINC(smem_base + sbuf * 8);
    };

    float acc[4][8][4];
    #pragma unroll
    for (int mt = 0; mt < 4; mt++)
        #pragma unroll
        for (int nt = 0; nt < 8; nt++)
            #pragma unroll
            for (int q = 0; q < 4; q++)
                acc[mt][nt][q] = 0.0f;

    // Producer state (per-thread, driven off the shared ring)
    int pseq = 0, lk = 0;
    int lt = s_tile[0];
    // Prologue: stages 0,1 of first tile (seq-1 fetch for seq 1 done above)
    load_stage(0, lt, 0);
    load_stage(1, lt, 1);
    lk = 2;

    int sb = 0, fpar = 0;     // consumer: buffer + full-parity
    int lb = 2, epar = 1;     // producer: buffer + empty-parity (first waits pass)

    int cseq = 0;
    int ctile = s_tile[0];
    while (ctile < NTILES) {
        for (int it = 0; it < KITERS; ++it) {
            // Producer: refill next buffer (waits only on 3-ago consumption)
            if (lt < NTILES) {
                // On tile start, steal the NEXT tile (16 iters of slack vs
                // warp skew <= ~3, so ring entries are settled before reads).
                if (lk == 0 && tid == 0)
                    s_tile[(pseq + 1) & 7] = atomicAdd(&g_tile_ctr, 1);
                MBAR_WAIT_RLX(smem_base + 24 + lb * 8, epar);
                load_stage(lb, lt, lk);
                if (++lk == KITERS) { lk = 0; ++pseq; lt = s_tile[pseq & 7]; }
                if (++lb == NSTAGE) { lb = 0; epar ^= 1; }
            }

            // Consumer: wait for this stage's data
            MBAR_WAIT(smem_base + sb * 8, fpar);

            const uint32_t sbase = smem_base + SMEM_ST0 + sb * STAGE_BYTES;
            #pragma unroll
            for (int ks = 0; ks < 4; ks++) {
                const uint32_t kb = ks * 32;
                uint32_t a[4][4];
                #pragma unroll
                for (int t = 0; t < 4; t++)
                    ldsm_x4(a[t], sbase + swz(a_rowoff[t] + kb + a_kb));
                uint32_t b[8][2];
                #pragma unroll
                for (int p = 0; p < 4; p++) {
                    uint32_t r[4];
                    ldsm_x4(r, sbase + swz(b_rowoff[p] + kb + b_kb));
                    b[2 * p][0] = r[0]; b[2 * p][1] = r[1];
                    b[2 * p + 1][0] = r[2]; b[2 * p + 1][1] = r[3];
                }
                #pragma unroll
                for (int mt = 0; mt < 4; mt++)
                    #pragma unroll
                    for (int nt = 0; nt < 8; nt++)
                        mma16816(acc[mt][nt], a[mt], b[nt]);
            }
            // This warp is done reading stage sb
            __syncwarp();
            if (lid == 0) MBAR_ARRIVE(smem_base + 24 + sb * 8);
            if (++sb == NSTAGE) { sb = 0; fpar ^= 1; }
        }

        // Epilogue for this tile (overlaps in-flight loads of next tile)
        {
            const int rowA0 = (ctile >> 5) * BM;
            const int rowB0 = (ctile & 31) * BN;
            const int crow = rowA0 + wm * 64 + (lid >> 2);
            const int ccol = rowB0 + wn * 64 + (lid & 3) * 2;
            #pragma unroll
            for (int mt = 0; mt < 4; mt++) {
                #pragma unroll
                for (int nt = 0; nt < 8; nt++) {
                    float* p0 = C + (size_t)(crow + mt * 16) * NROWS + ccol + nt * 8;
                    float* p1 = p0 + 8 * NROWS;
                    *(float2*)p0 = make_float2(acc[mt][nt][0], acc[mt][nt][1]);
                    *(float2*)p1 = make_float2(acc[mt][nt][2], acc[mt][nt][3]);
                    acc[mt][nt][0] = 0.0f; acc[mt][nt][1] = 0.0f;
                    acc[mt][nt][2] = 0.0f; acc[mt][nt][3] = 0.0f;
                }
            }
        }
        ++cseq;
        ctile = s_tile[cseq & 7];
    }
}

// ---------------------------------------------------------------------------
extern "C" void kernel_launch(void* const* d_in, const int* in_sizes, int n_in,
                              void* d_out, int out_size) {
    const float* x = (const float*)d_in[0];
    const float* y = (const float*)d_in[1];
    float* out = (float*)d_out;

    cudaFuncSetAttribute(gemm_kernel, cudaFuncAttributeMaxDynamicSharedMemorySize, SMEM_DYN);

    norm_kernel<<<2 * NROWS, 256>>>(x, y);
    gemm_kernel<<<GRID_P, NTHREADS, SMEM_DYN>>>(out);
}

// round 14
// speedup vs baseline: 1.1326x; 1.0024x over previous
#include <cuda_runtime.h>
#include <cuda_fp16.h>
#include <cstdint>

// CosSimilarity via fp16 mma.sync (legacy HMMA; tcgen05 unavailable: harness
// ptxas targets plain sm_103).
//  K1: normalize rows (x side pre-scaled by 1/TEMP=20) -> fp16 scratch.
//  K2: persistent HMMA GEMM (R8 config: BM=BN=128, BK=64, 3-stage mbarrier
//      cp.async pipeline, 128-thread CTAs, 2x2 of 64x64 warp tiles, 2 CTA/SM).
//      NEW (R14): anti-phase jitter. The two co-resident CTAs per SM run
//      identical instruction streams in lockstep, so both warps on each SMSP
//      hit the iteration-top dead zone (waits+ldsm+cp.async, ~840 cyc of a
//      2890-cyc period) simultaneously -> tensor pipe idles 29%. Odd CTAs
//      spin ~1400 cyc (half period) once at startup to break the symmetry so
//      each warp's dead zone lands under the partner's HMMA burst.

#define NROWS 4096
#define DDIM  1024
#define BM 128
#define BN 128
#define BK 64
#define NSTAGE 3
#define KITERS (DDIM / BK)              // 16
#define STAGE_BYTES ((BM + BN) * 128)   // 32 KB
#define SMEM_ST0 1024
#define SMEM_DYN (SMEM_ST0 + NSTAGE * STAGE_BYTES)
#define NTILES ((NROWS / BM) * (NROWS / BN))   // 1024
#define GRID_P 296                      // 2 x 148 SMs
#define NTHREADS 128
#define JITTER_CYC 1400

__device__ __align__(1024) __half g_xh[NROWS * DDIM];
__device__ __align__(1024) __half g_yh[NROWS * DDIM];

__device__ __forceinline__ uint32_t smem_u32(const void* p) {
    uint32_t a;
    asm("{ .reg .u64 t; cvta.to.shared.u64 t, %1; cvt.u32.u64 %0, t; }" : "=r"(a) : "l"(p));
    return a;
}

#define CP_ASYNC16(dst, src) \
    asm volatile("cp.async.cg.shared.global [%0], [%1], 16;" :: "r"(dst), "l"(src))
#define CP_ASYNC_ARRIVE_NOINC(mbar) \
    asm volatile("cp.async.mbarrier.arrive.noinc.shared.b64 [%0];" :: "r"(mbar) : "memory")

#define MBAR_INIT(addr, cnt) \
    asm volatile("mbarrier.init.shared.b64 [%0], %1;" :: "r"(addr), "r"(cnt) : "memory")
#define MBAR_ARRIVE(addr) \
    asm volatile("mbarrier.arrive.shared.b64 _, [%0];" :: "r"(addr) : "memory")

#define MBAR_WAIT(addr, par) do {                                                  \
    uint32_t _m = (addr); uint32_t _p = (par); uint32_t _done;                     \
    asm volatile("{\n\t.reg .pred p;\n\t"                                          \
        "mbarrier.try_wait.parity.acquire.cta.shared::cta.b64 p, [%1], %2;\n\t"    \
        "selp.b32 %0, 1, 0, p;\n\t}"                                               \
        : "=r"(_done) : "r"(_m), "r"(_p) : "memory");                              \
    if (!_done) {                                                                  \
        asm volatile("{\n\t.reg .pred P1;\n\t"                                     \
            "WL_%=:\n\t"                                                           \
            "mbarrier.try_wait.parity.acquire.cta.shared::cta.b64 P1, [%0], %1, 0x989680;\n\t" \
            "@P1 bra.uni WD_%=;\n\t"                                               \
            "bra.uni WL_%=;\n\t"                                                   \
            "WD_%=:\n\t}" :: "r"(_m), "r"(_p) : "memory");                         \
    }                                                                              \
} while (0)

#define MBAR_WAIT_RLX(addr, par) do {                                              \
    uint32_t _m = (addr); uint32_t _p = (par); uint32_t _done;                     \
    asm volatile("{\n\t.reg .pred p;\n\t"                                          \
        "mbarrier.try_wait.parity.relaxed.cta.shared::cta.b64 p, [%1], %2, 0x989680;\n\t" \
        "selp.b32 %0, 1, 0, p;\n\t}"                                               \
        : "=r"(_done) : "r"(_m), "r"(_p) : "memory");                              \
    if (!_done) {                                                                  \
        asm volatile("{\n\t.reg .pred P1;\n\t"                                     \
            "WL_%=:\n\t"                                                           \
            "mbarrier.try_wait.parity.relaxed.cta.shared::cta.b64 P1, [%0], %1, 0x989680;\n\t" \
            "@P1 bra.uni WD_%=;\n\t"                                               \
            "bra.uni WL_%=;\n\t"                                                   \
            "WD_%=:\n\t}" :: "r"(_m), "r"(_p) : "memory");                         \
    }                                                                              \
} while (0)

__device__ __forceinline__ uint32_t swz(uint32_t off) {
    return off ^ ((off >> 3) & 0x70);
}

__device__ __forceinline__ void ldsm_x4(uint32_t* r, uint32_t addr) {
    asm volatile("ldmatrix.sync.aligned.m8n8.x4.shared.b16 {%0,%1,%2,%3}, [%4];"
                 : "=r"(r[0]), "=r"(r[1]), "=r"(r[2]), "=r"(r[3]) : "r"(addr));
}

__device__ __forceinline__ void mma16816(float* c, const uint32_t* a, const uint32_t* b) {
    asm volatile(
        "mma.sync.aligned.m16n8k16.row.col.f32.f16.f16.f32 "
        "{%0,%1,%2,%3}, {%4,%5,%6,%7}, {%8,%9}, {%0,%1,%2,%3};"
        : "+f"(c[0]), "+f"(c[1]), "+f"(c[2]), "+f"(c[3])
        : "r"(a[0]), "r"(a[1]), "r"(a[2]), "r"(a[3]), "r"(b[0]), "r"(b[1]));
}

// ---------------------------------------------------------------------------
// Kernel 1: row normalization -> fp16 (one 256-thread block per row)
// ---------------------------------------------------------------------------
__global__ void norm_kernel(const float* __restrict__ x, const float* __restrict__ y) {
    int row = blockIdx.x;
    const float4* src; __half2* dst; float extra;
    if (row < NROWS) {
        src = (const float4*)(x + (size_t)row * DDIM);
        dst = (__half2*)(g_xh + (size_t)row * DDIM);
        extra = 20.0f;                  // 1/TEMP folded into x side
    } else {
        int r = row - NROWS;
        src = (const float4*)(y + (size_t)r * DDIM);
        dst = (__half2*)(g_yh + (size_t)r * DDIM);
        extra = 1.0f;
    }
    int t = threadIdx.x;
    float4 v = src[t];
    float ss = v.x * v.x + v.y * v.y + v.z * v.z + v.w * v.w;
    #pragma unroll
    for (int o = 16; o > 0; o >>= 1) ss += __shfl_xor_sync(0xffffffffu, ss, o);

    __shared__ float wss[8];
    __shared__ float sinv;
    if ((t & 31) == 0) wss[t >> 5] = ss;
    __syncthreads();
    if (t == 0) {
        float tot = 0.0f;
        #pragma unroll
        for (int i = 0; i < 8; i++) tot += wss[i];
        sinv = extra / fmaxf(sqrtf(tot), 1e-8f);
    }
    __syncthreads();
    float inv = sinv;
    dst[2 * t]     = __floats2half2_rn(v.x * inv, v.y * inv);
    dst[2 * t + 1] = __floats2half2_rn(v.z * inv, v.w * inv);
}

// ---------------------------------------------------------------------------
// Kernel 2: persistent HMMA GEMM, 4 warps/CTA, warp tile 64x64, 2 CTA/SM,
//           anti-phase startup jitter for odd CTAs
// ---------------------------------------------------------------------------
__global__ void __launch_bounds__(NTHREADS, 2) gemm_kernel(float* __restrict__ C) {
    extern __shared__ __align__(1024) char smem[];
    const uint32_t smem_base = smem_u32(smem);
    const int tid = threadIdx.x;
    const int wid = tid >> 5;
    const int lid = tid & 31;

    const int wm = wid & 1;              // m band (64 rows each)
    const int wn = wid >> 1;             // n band (64 cols each)

    // barriers: full[s] @ base + s*8 ; empty[s] @ base + 24 + s*8
    if (tid == 0) {
        #pragma unroll
        for (int s = 0; s < NSTAGE; s++) {
            MBAR_INIT(smem_base + s * 8, NTHREADS); // full: one noinc arrive/thread
            MBAR_INIT(smem_base + 24 + s * 8, 4);   // empty: one arrive/warp
        }
    }
    __syncthreads();

    // Anti-phase jitter: odd CTAs delay ~half an iteration period so the two
    // co-resident CTAs' dead zones interleave with each other's HMMA bursts.
    if (blockIdx.x & 1) {
        unsigned long long t0 = clock64();
        while (clock64() - t0 < JITTER_CYC) { }
    }

    // ldmatrix lane geometry
    const int g   = lid >> 3;
    const int rin = lid & 7;
    const int a_m  = (g & 1) * 8 + rin;
    const int a_kb = (g >> 1) * 16;
    const int b_n  = (g >> 1) * 8 + rin;
    const int b_kb = (g & 1) * 16;

    uint32_t a_rowoff[4], b_rowoff[4];
    #pragma unroll
    for (int t = 0; t < 4; t++)
        a_rowoff[t] = (uint32_t)(wm * 64 + t * 16 + a_m) * 128;
    #pragma unroll
    for (int p = 0; p < 4; p++)
        b_rowoff[p] = (uint32_t)(BM + wn * 64 + p * 16 + b_n) * 128;

    // Stage loader for (tile lt, k-slice lk): 2048 chunks / 128 thr = 16 each.
    auto load_stage = [&](int sbuf, int lt, int lk) {
        uint32_t sbase = smem_base + SMEM_ST0 + sbuf * STAGE_BYTES;
        const char* ag = (const char*)g_xh
            + ((size_t)(lt >> 5) * BM) * (DDIM * 2) + lk * (BK * 2);
        const char* bg = (const char*)g_yh
            + ((size_t)(lt & 31) * BN) * (DDIM * 2) + lk * (BK * 2);
        #pragma unroll
        for (int k = 0; k < 16; k++) {
            int i = tid + k * NTHREADS;
            int r = (i >> 3) & 127;
            int c = (i & 7) * 16;
            uint32_t off = swz((uint32_t)((i < 1024 ? r : BM + r) * 128 + c));
            const char* src = (i < 1024 ? ag : bg) + (size_t)r * (DDIM * 2) + c;
            CP_ASYNC16(sbase + off, src);
        }
        CP_ASYNC_ARRIVE_NOINC(smem_base + sbuf * 8);
    };

    float acc[4][8][4];
    #pragma unroll
    for (int mt = 0; mt < 4; mt++)
        #pragma unroll
        for (int nt = 0; nt < 8; nt++)
            #pragma unroll
            for (int q = 0; q < 4; q++)
                acc[mt][nt][q] = 0.0f;

    int tile = blockIdx.x;
    int lt = tile, lk = 0;
    // Prologue: stages 0,1 of first tile (fresh empty barriers: no wait needed)
    load_stage(0, lt, 0);
    load_stage(1, lt, 1);
    lk = 2;

    int sb = 0, fpar = 0;     // consumer: buffer + full-parity
    int lb = 2, epar = 1;     // producer: buffer + empty-parity (first waits pass)
    while (tile < NTILES) {
        for (int it = 0; it < KITERS; ++it) {
            // Producer: refill next buffer (waits only on 3-ago consumption)
            if (lt < NTILES) {
                MBAR_WAIT_RLX(smem_base + 24 + lb * 8, epar);
                load_stage(lb, lt, lk);
                if (++lk == KITERS) { lk = 0; lt += GRID_P; }
                if (++lb == NSTAGE) { lb = 0; epar ^= 1; }
            }

            // Consumer: wait for this stage's data
            MBAR_WAIT(smem_base + sb * 8, fpar);

            const uint32_t sbase = smem_base + SMEM_ST0 + sb * STAGE_BYTES;
            #pragma unroll
            for (int ks = 0; ks < 4; ks++) {
                const uint32_t kb = ks * 32;
                uint32_t a[4][4];
                #pragma unroll
                for (int t = 0; t < 4; t++)
                    ldsm_x4(a[t], sbase + swz(a_rowoff[t] + kb + a_kb));
                uint32_t b[8][2];
                #pragma unroll
                for (int p = 0; p < 4; p++) {
                    uint32_t r[4];
                    ldsm_x4(r, sbase + swz(b_rowoff[p] + kb + b_kb));
                    b[2 * p][0] = r[0]; b[2 * p][1] = r[1];
                    b[2 * p + 1][0] = r[2]; b[2 * p + 1][1] = r[3];
                }
                #pragma unroll
                for (int mt = 0; mt < 4; mt++)
                    #pragma unroll
                    for (int nt = 0; nt < 8; nt++)
                        mma16816(acc[mt][nt], a[mt], b[nt]);
            }
            // This warp is done reading stage sb
            __syncwarp();
            if (lid == 0) MBAR_ARRIVE(smem_base + 24 + sb * 8);
            if (++sb == NSTAGE) { sb = 0; fpar ^= 1; }
        }

        // Epilogue for this tile (overlaps in-flight loads of next tile)
        {
            const int rowA0 = (tile >> 5) * BM;
            const int rowB0 = (tile & 31) * BN;
            const int crow = rowA0 + wm * 64 + (lid >> 2);
            const int ccol = rowB0 + wn * 64 + (lid & 3) * 2;
            #pragma unroll
            for (int mt = 0; mt < 4; mt++) {
                #pragma unroll
                for (int nt = 0; nt < 8; nt++) {
                    float* p0 = C + (size_t)(crow + mt * 16) * NROWS + ccol + nt * 8;
                    float* p1 = p0 + 8 * NROWS;
                    *(float2*)p0 = make_float2(acc[mt][nt][0], acc[mt][nt][1]);
                    *(float2*)p1 = make_float2(acc[mt][nt][2], acc[mt][nt][3]);
                    acc[mt][nt][0] = 0.0f; acc[mt][nt][1] = 0.0f;
                    acc[mt][nt][2] = 0.0f; acc[mt][nt][3] = 0.0f;
                }
            }
        }
        tile += GRID_P;
    }
}

// ---------------------------------------------------------------------------
extern "C" void kernel_launch(void* const* d_in, const int* in_sizes, int n_in,
                              void* d_out, int out_size) {
    const float* x = (const float*)d_in[0];
    const float* y = (const float*)d_in[1];
    float* out = (float*)d_out;

    cudaFuncSetAttribute(gemm_kernel, cudaFuncAttributeMaxDynamicSharedMemorySize, SMEM_DYN);

    norm_kernel<<<2 * NROWS, 256>>>(x, y);
    gemm_kernel<<<GRID_P, NTHREADS, SMEM_DYN>>>(out);
}